// round 1
// baseline (speedup 1.0000x reference)
#include <cuda_runtime.h>
#include <cuda_bf16.h>

#define NUM_USERS 100000
#define NUM_ITEMS 50000
#define N_NODES   150000
#define DIM       64
#define N_EDGES   4800000
#define K_HOPS    3

// ---------------- static device scratch (no dynamic allocation allowed) ----
__device__ float g_bufA[(size_t)N_NODES * DIM];   // ping
__device__ float g_bufB[(size_t)N_NODES * DIM];   // pong
__device__ float g_acc [(size_t)N_NODES * DIM];   // running sum of hops
__device__ int   g_rowptr[N_NODES + 1];
__device__ int   g_cnt [N_NODES];
__device__ int   g_fill[N_NODES];
__device__ int   g_col [N_EDGES];
__device__ float g_w   [N_EDGES];
__device__ int   g_is64;

// ---------------- dtype detection: int64 vs int32 edge_index ---------------
// Values are node ids < 150000 (< 2^31). If the buffer is int64 (little
// endian), every odd 32-bit word of the first 32 elements is 0. If it is
// int32, those words are random node ids — probability all 32 are zero is
// ~(1/150000)^32 ~ 0.
__global__ void k_detect(const int* __restrict__ ei32) {
    int lane = threadIdx.x;
    int v = ei32[2 * lane + 1];
    unsigned b = __ballot_sync(0xffffffffu, v == 0);
    if (lane == 0) g_is64 = (b == 0xffffffffu) ? 1 : 0;
}

__device__ __forceinline__ int load_edge_idx(const void* ei, long long i, int is64) {
    if (is64) return (int)((const long long*)ei)[i];
    return ((const int*)ei)[i];
}

// ---------------- init: emb0 = concat(users, items); acc = emb0; cnt = 0 ---
__global__ void k_init(const float* __restrict__ users,
                       const float* __restrict__ items) {
    int i = blockIdx.x * blockDim.x + threadIdx.x;
    const int total = N_NODES * DIM;
    const int usz = NUM_USERS * DIM;
    if (i < total) {
        float v = (i < usz) ? users[i] : items[i - usz];
        g_bufA[i] = v;
        g_acc[i]  = v;
    }
    if (i < N_NODES) g_cnt[i] = 0;
}

// ---------------- histogram of destination rows ----------------------------
__global__ void k_count(const void* __restrict__ ei) {
    int is64 = g_is64;
    int e = blockIdx.x * blockDim.x + threadIdx.x;
    if (e < N_EDGES) {
        int r = load_edge_idx(ei, e, is64);
        atomicAdd(&g_cnt[r], 1);
    }
}

// ---------------- single-block exclusive scan over 150000 counts -----------
__global__ void k_scan() {
    __shared__ int ssum[1024];
    const int T = 1024;
    const int CH = (N_NODES + T - 1) / T;  // 147
    int t = threadIdx.x;
    int lo = t * CH;
    int hi = lo + CH; if (hi > N_NODES) hi = N_NODES;
    int s = 0;
    for (int i = lo; i < hi; ++i) s += g_cnt[i];
    ssum[t] = s;
    __syncthreads();
    // inclusive Hillis-Steele scan of per-thread sums
    for (int off = 1; off < T; off <<= 1) {
        int v = (t >= off) ? ssum[t - off] : 0;
        __syncthreads();
        ssum[t] += v;
        __syncthreads();
    }
    int run = (t == 0) ? 0 : ssum[t - 1];
    for (int i = lo; i < hi; ++i) {
        g_rowptr[i] = run;
        g_fill[i]   = run;
        run += g_cnt[i];
    }
    if (t == T - 1) g_rowptr[N_NODES] = ssum[T - 1];
}

// ---------------- scatter edges into CSR -----------------------------------
__global__ void k_scatter(const void* __restrict__ ei,
                          const float* __restrict__ ew) {
    int is64 = g_is64;
    int e = blockIdx.x * blockDim.x + threadIdx.x;
    if (e < N_EDGES) {
        int r = load_edge_idx(ei, e, is64);
        int c = load_edge_idx(ei, (long long)N_EDGES + e, is64);
        int pos = atomicAdd(&g_fill[r], 1);
        g_col[pos] = c;
        g_w[pos]   = ew[e];
    }
}

// ---------------- pull-based SpMM: one warp per destination node -----------
// srcSel==0: src=g_bufA, dst=g_bufB ;  srcSel==1: src=g_bufB, dst=g_bufA
// Each lane owns 2 consecutive dims (float2). Edge (col,w) staged in
// registers 32 at a time, broadcast via shfl. Also fuses acc += dst.
__global__ void __launch_bounds__(256) k_spmm(int srcSel) {
    const float* __restrict__ src = srcSel ? g_bufB : g_bufA;
    float*       __restrict__ dst = srcSel ? g_bufA : g_bufB;

    int warp = (blockIdx.x * blockDim.x + threadIdx.x) >> 5;
    int lane = threadIdx.x & 31;
    if (warp >= N_NODES) return;

    int start = g_rowptr[warp];
    int end   = g_rowptr[warp + 1];

    float a0 = 0.f, a1 = 0.f;

    for (int base = start; base < end; base += 32) {
        int j = base + lane;
        int   c  = 0;
        float ww = 0.f;
        if (j < end) { c = g_col[j]; ww = g_w[j]; }
        int m = end - base; if (m > 32) m = 32;
        #pragma unroll 4
        for (int k = 0; k < m; ++k) {
            int   cc = __shfl_sync(0xffffffffu, c,  k);
            float wk = __shfl_sync(0xffffffffu, ww, k);
            float2 v = *(const float2*)(src + ((size_t)cc << 6) + 2 * lane);
            a0 = fmaf(wk, v.x, a0);
            a1 = fmaf(wk, v.y, a1);
        }
    }

    size_t o = ((size_t)warp << 6) + 2 * lane;
    *(float2*)(dst + o) = make_float2(a0, a1);
    float2 ac = *(const float2*)(g_acc + o);
    *(float2*)(g_acc + o) = make_float2(ac.x + a0, ac.y + a1);
}

// ---------------- assemble output ------------------------------------------
// out = [u_final (6.4M) | users_emb (6.4M) | i_final (3.2M) | items_emb (3.2M)]
__global__ void k_final(const float* __restrict__ users,
                        const float* __restrict__ items,
                        float* __restrict__ out) {
    const int U = NUM_USERS * DIM;  // 6,400,000
    const int I = NUM_ITEMS * DIM;  // 3,200,000
    int i = blockIdx.x * blockDim.x + threadIdx.x;
    const int total = 2 * (U + I);
    if (i >= total) return;
    float v;
    if (i < U) {
        v = g_acc[i] * 0.25f;
    } else if (i < 2 * U) {
        v = users[i - U];
    } else if (i < 2 * U + I) {
        v = g_acc[U + (i - 2 * U)] * 0.25f;
    } else {
        v = items[i - (2 * U + I)];
    }
    out[i] = v;
}

// ---------------- launch ----------------------------------------------------
extern "C" void kernel_launch(void* const* d_in, const int* in_sizes, int n_in,
                              void* d_out, int out_size) {
    const float* users = (const float*)d_in[0];
    const float* items = (const float*)d_in[1];
    const void*  ei    = d_in[2];   // int64 or int32, detected on device
    const float* ew    = (const float*)d_in[3];
    float* out = (float*)d_out;

    k_detect<<<1, 32>>>((const int*)ei);

    {   // init emb0/acc and zero counts
        int total = N_NODES * DIM;
        k_init<<<(total + 255) / 256, 256>>>(users, items);
    }

    k_count<<<(N_EDGES + 255) / 256, 256>>>(ei);
    k_scan<<<1, 1024>>>();
    k_scatter<<<(N_EDGES + 255) / 256, 256>>>(ei, ew);

    {   // 3 hops, ping-pong A<->B, acc fused inside
        int threads = N_NODES * 32;
        int blocks = (threads + 255) / 256;
        k_spmm<<<blocks, 256>>>(0);  // A -> B
        k_spmm<<<blocks, 256>>>(1);  // B -> A
        k_spmm<<<blocks, 256>>>(0);  // A -> B
    }

    {
        int total = 2 * (NUM_USERS * DIM + NUM_ITEMS * DIM);
        k_final<<<(total + 255) / 256, 256>>>(users, items, out);
    }
}

// round 2
// speedup vs baseline: 1.4514x; 1.4514x over previous
#include <cuda_runtime.h>
#include <cuda_bf16.h>

#define NUM_USERS 100000
#define NUM_ITEMS 50000
#define N_NODES   150000
#define DIM       64
#define N_EDGES   4800000
#define K_HOPS    3

#define SCAN_TILE 1024
#define SCAN_NBLK ((N_NODES + SCAN_TILE - 1) / SCAN_TILE)   // 147

// ---------------- static device scratch (no dynamic allocation allowed) ----
__device__ float g_bufA[(size_t)N_NODES * DIM];   // ping
__device__ float g_bufB[(size_t)N_NODES * DIM];   // pong
__device__ float g_acc [(size_t)N_NODES * DIM];   // running sum of hops
__device__ int   g_rowptr[N_NODES + 1];
__device__ int   g_cnt [N_NODES];
__device__ int   g_fill[N_NODES];
__device__ int   g_part[SCAN_NBLK];
__device__ int   g_col [N_EDGES];
__device__ float g_w   [N_EDGES];
__device__ int   g_is64;

// ---------------- dtype detection: int64 vs int32 edge_index ---------------
// Node ids < 150000 (< 2^31). If the buffer is little-endian int64, every odd
// 32-bit word of the first 32 elements is 0; for int32 that's ~impossible.
__global__ void k_detect(const int* __restrict__ ei32) {
    int lane = threadIdx.x;
    int v = ei32[2 * lane + 1];
    unsigned b = __ballot_sync(0xffffffffu, v == 0);
    if (lane == 0) g_is64 = (b == 0xffffffffu) ? 1 : 0;
}

__device__ __forceinline__ int load_edge_idx(const void* ei, long long i, int is64) {
    if (is64) return (int)((const long long*)ei)[i];
    return ((const int*)ei)[i];
}

// ---------------- init: emb0 = concat(users, items); acc = emb0; cnt = 0 ---
__global__ void k_init(const float* __restrict__ users,
                       const float* __restrict__ items) {
    int i = blockIdx.x * blockDim.x + threadIdx.x;
    const int total = N_NODES * DIM;
    const int usz = NUM_USERS * DIM;
    if (i < total) {
        float v = (i < usz) ? users[i] : items[i - usz];
        g_bufA[i] = v;
        g_acc[i]  = v;
    }
    if (i < N_NODES) g_cnt[i] = 0;
}

// ---------------- histogram of destination rows ----------------------------
__global__ void k_count(const void* __restrict__ ei) {
    int is64 = g_is64;
    int e = blockIdx.x * blockDim.x + threadIdx.x;
    if (e < N_EDGES) {
        int r = load_edge_idx(ei, e, is64);
        atomicAdd(&g_cnt[r], 1);
    }
}

// ---------------- 3-phase chip-wide exclusive scan over g_cnt --------------
// Phase 1: per-block (1024-elem tile) total
__global__ void k_partials() {
    __shared__ int sh[256];
    int b = blockIdx.x, t = threadIdx.x;
    int base = b * SCAN_TILE + t * 4;
    int s = 0;
    #pragma unroll
    for (int k = 0; k < 4; ++k) {
        int i = base + k;
        if (i < N_NODES) s += g_cnt[i];
    }
    sh[t] = s;
    __syncthreads();
    for (int off = 128; off > 0; off >>= 1) {
        if (t < off) sh[t] += sh[t + off];
        __syncthreads();
    }
    if (t == 0) g_part[b] = sh[0];
}

// Phase 2: scan the 147 block totals (one small block)
__global__ void k_scanparts() {
    __shared__ int sh[256];
    int t = threadIdx.x;
    int v = (t < SCAN_NBLK) ? g_part[t] : 0;
    sh[t] = v;
    __syncthreads();
    for (int off = 1; off < 256; off <<= 1) {
        int x = (t >= off) ? sh[t - off] : 0;
        __syncthreads();
        sh[t] += x;
        __syncthreads();
    }
    if (t < SCAN_NBLK) g_part[t] = sh[t] - v;          // exclusive
    if (t == SCAN_NBLK - 1) g_rowptr[N_NODES] = sh[t]; // grand total
}

// Phase 3: per-block local exclusive scan + global offset, write rowptr/fill
__global__ void k_writeptr() {
    __shared__ int sh[256];
    int b = blockIdx.x, t = threadIdx.x;
    int base = b * SCAN_TILE + t * 4;
    int c0 = 0, c1 = 0, c2 = 0, c3 = 0;
    if (base + 0 < N_NODES) c0 = g_cnt[base + 0];
    if (base + 1 < N_NODES) c1 = g_cnt[base + 1];
    if (base + 2 < N_NODES) c2 = g_cnt[base + 2];
    if (base + 3 < N_NODES) c3 = g_cnt[base + 3];
    int s = c0 + c1 + c2 + c3;
    sh[t] = s;
    __syncthreads();
    for (int off = 1; off < 256; off <<= 1) {
        int x = (t >= off) ? sh[t - off] : 0;
        __syncthreads();
        sh[t] += x;
        __syncthreads();
    }
    int run = g_part[b] + (sh[t] - s);   // exclusive within block + block offset
    if (base + 0 < N_NODES) { g_rowptr[base + 0] = run; g_fill[base + 0] = run; run += c0; }
    if (base + 1 < N_NODES) { g_rowptr[base + 1] = run; g_fill[base + 1] = run; run += c1; }
    if (base + 2 < N_NODES) { g_rowptr[base + 2] = run; g_fill[base + 2] = run; run += c2; }
    if (base + 3 < N_NODES) { g_rowptr[base + 3] = run; g_fill[base + 3] = run; run += c3; }
}

// ---------------- scatter edges into CSR -----------------------------------
__global__ void k_scatter(const void* __restrict__ ei,
                          const float* __restrict__ ew) {
    int is64 = g_is64;
    int e = blockIdx.x * blockDim.x + threadIdx.x;
    if (e < N_EDGES) {
        int r = load_edge_idx(ei, e, is64);
        int c = load_edge_idx(ei, (long long)N_EDGES + e, is64);
        int pos = atomicAdd(&g_fill[r], 1);
        g_col[pos] = c;
        g_w[pos]   = ew[e];
    }
}

// ---------------- pull-based SpMM: one warp per destination node -----------
// srcSel==0: src=g_bufA, dst=g_bufB ;  srcSel==1: src=g_bufB, dst=g_bufA
// Lane owns 2 consecutive dims (float2). Edge (col,w) staged in registers 32
// at a time, broadcast via shfl. Fuses acc += result. writeDst==0 on the
// final hop (only acc is needed).
__global__ void __launch_bounds__(256) k_spmm(int srcSel, int writeDst) {
    const float* __restrict__ src = srcSel ? g_bufB : g_bufA;
    float*       __restrict__ dst = srcSel ? g_bufA : g_bufB;

    int warp = (blockIdx.x * blockDim.x + threadIdx.x) >> 5;
    int lane = threadIdx.x & 31;
    if (warp >= N_NODES) return;

    int start = g_rowptr[warp];
    int end   = g_rowptr[warp + 1];

    float a0 = 0.f, a1 = 0.f;

    for (int base = start; base < end; base += 32) {
        int j = base + lane;
        int   c  = 0;
        float ww = 0.f;
        if (j < end) { c = g_col[j]; ww = g_w[j]; }
        int m = end - base; if (m > 32) m = 32;
        #pragma unroll 4
        for (int k = 0; k < m; ++k) {
            int   cc = __shfl_sync(0xffffffffu, c,  k);
            float wk = __shfl_sync(0xffffffffu, ww, k);
            float2 v = *(const float2*)(src + ((size_t)cc << 6) + 2 * lane);
            a0 = fmaf(wk, v.x, a0);
            a1 = fmaf(wk, v.y, a1);
        }
    }

    size_t o = ((size_t)warp << 6) + 2 * lane;
    if (writeDst) *(float2*)(dst + o) = make_float2(a0, a1);
    float2 ac = *(const float2*)(g_acc + o);
    *(float2*)(g_acc + o) = make_float2(ac.x + a0, ac.y + a1);
}

// ---------------- assemble output ------------------------------------------
// out = [u_final (6.4M) | users_emb (6.4M) | i_final (3.2M) | items_emb (3.2M)]
__global__ void k_final(const float* __restrict__ users,
                        const float* __restrict__ items,
                        float* __restrict__ out) {
    const int U = NUM_USERS * DIM;  // 6,400,000
    const int I = NUM_ITEMS * DIM;  // 3,200,000
    int i = blockIdx.x * blockDim.x + threadIdx.x;
    const int total = 2 * (U + I);
    if (i >= total) return;
    float v;
    if (i < U) {
        v = g_acc[i] * 0.25f;
    } else if (i < 2 * U) {
        v = users[i - U];
    } else if (i < 2 * U + I) {
        v = g_acc[U + (i - 2 * U)] * 0.25f;
    } else {
        v = items[i - (2 * U + I)];
    }
    out[i] = v;
}

// ---------------- launch ----------------------------------------------------
extern "C" void kernel_launch(void* const* d_in, const int* in_sizes, int n_in,
                              void* d_out, int out_size) {
    const float* users = (const float*)d_in[0];
    const float* items = (const float*)d_in[1];
    const void*  ei    = d_in[2];   // int64 or int32, detected on device
    const float* ew    = (const float*)d_in[3];
    float* out = (float*)d_out;

    k_detect<<<1, 32>>>((const int*)ei);

    {   // init emb0/acc and zero counts
        int total = N_NODES * DIM;
        k_init<<<(total + 255) / 256, 256>>>(users, items);
    }

    k_count<<<(N_EDGES + 255) / 256, 256>>>(ei);

    // 3-phase parallel exclusive scan (replaces the 238us single-block scan)
    k_partials <<<SCAN_NBLK, 256>>>();
    k_scanparts<<<1, 256>>>();
    k_writeptr <<<SCAN_NBLK, 256>>>();

    k_scatter<<<(N_EDGES + 255) / 256, 256>>>(ei, ew);

    {   // 3 hops, ping-pong A<->B, acc fused inside; last hop skips dst store
        int threads = N_NODES * 32;
        int blocks = (threads + 255) / 256;
        k_spmm<<<blocks, 256>>>(0, 1);  // A -> B
        k_spmm<<<blocks, 256>>>(1, 1);  // B -> A
        k_spmm<<<blocks, 256>>>(0, 0);  // A -> acc only
    }

    {
        int total = 2 * (NUM_USERS * DIM + NUM_ITEMS * DIM);
        k_final<<<(total + 255) / 256, 256>>>(users, items, out);
    }
}

// round 3
// speedup vs baseline: 1.8342x; 1.2637x over previous
#include <cuda_runtime.h>
#include <cuda_bf16.h>

#define NUM_USERS 100000
#define NUM_ITEMS 50000
#define N_NODES   150000
#define DIM       64
#define N_EDGES   4800000

#define U_ELEMS (NUM_USERS * DIM)   // 6,400,000
#define I_ELEMS (NUM_ITEMS * DIM)   // 3,200,000

#define SCAN_TILE 1024
#define SCAN_NBLK ((N_NODES + SCAN_TILE - 1) / SCAN_TILE)   // 147

// ---------------- static device scratch (no dynamic allocation allowed) ----
__device__ float g_bufA[(size_t)N_NODES * DIM];   // emb0
__device__ float g_bufB[(size_t)N_NODES * DIM];   // h1
__device__ float g_bufC[(size_t)N_NODES * DIM];   // h2
__device__ int   g_rowptr[N_NODES + 1];
__device__ int   g_cnt [N_NODES];
__device__ int   g_fill[N_NODES];
__device__ int   g_part[SCAN_NBLK];
__device__ int2  g_cw  [N_EDGES];                 // interleaved {col, w_bits}
__device__ int   g_is64;

// ---------------- dtype detection: int64 vs int32 edge_index ---------------
// Node ids < 150000 (< 2^31). If the buffer is little-endian int64, every odd
// 32-bit word of the first 32 elements is 0; for int32 that's ~impossible.
__global__ void k_detect(const int* __restrict__ ei32) {
    int lane = threadIdx.x;
    int v = ei32[2 * lane + 1];
    unsigned b = __ballot_sync(0xffffffffu, v == 0);
    if (lane == 0) g_is64 = (b == 0xffffffffu) ? 1 : 0;
}

__device__ __forceinline__ int load_edge_idx(const void* ei, long long i, int is64) {
    if (is64) return (int)((const long long*)ei)[i];
    return ((const int*)ei)[i];
}

// ---------------- init: emb0 -> A; echo copies -> out; cnt = 0 -------------
// out layout: [u_final | users_emb | i_final | items_emb]
__global__ void k_init(const float* __restrict__ users,
                       const float* __restrict__ items,
                       float* __restrict__ out) {
    int i = blockIdx.x * blockDim.x + threadIdx.x;
    const int total = N_NODES * DIM;
    if (i < total) {
        float v;
        if (i < U_ELEMS) {
            v = users[i];
            out[U_ELEMS + i] = v;                       // users_emb echo
        } else {
            v = items[i - U_ELEMS];
            out[2 * U_ELEMS + I_ELEMS + (i - U_ELEMS)] = v;  // items_emb echo
        }
        g_bufA[i] = v;
    }
    if (i < N_NODES) g_cnt[i] = 0;
}

// ---------------- histogram of destination rows ----------------------------
__global__ void k_count(const void* __restrict__ ei) {
    int is64 = g_is64;
    int e = blockIdx.x * blockDim.x + threadIdx.x;
    if (e < N_EDGES) {
        int r = load_edge_idx(ei, e, is64);
        atomicAdd(&g_cnt[r], 1);
    }
}

// ---------------- 3-phase chip-wide exclusive scan over g_cnt --------------
__global__ void k_partials() {
    __shared__ int sh[256];
    int b = blockIdx.x, t = threadIdx.x;
    int base = b * SCAN_TILE + t * 4;
    int s = 0;
    #pragma unroll
    for (int k = 0; k < 4; ++k) {
        int i = base + k;
        if (i < N_NODES) s += g_cnt[i];
    }
    sh[t] = s;
    __syncthreads();
    for (int off = 128; off > 0; off >>= 1) {
        if (t < off) sh[t] += sh[t + off];
        __syncthreads();
    }
    if (t == 0) g_part[b] = sh[0];
}

__global__ void k_scanparts() {
    __shared__ int sh[256];
    int t = threadIdx.x;
    int v = (t < SCAN_NBLK) ? g_part[t] : 0;
    sh[t] = v;
    __syncthreads();
    for (int off = 1; off < 256; off <<= 1) {
        int x = (t >= off) ? sh[t - off] : 0;
        __syncthreads();
        sh[t] += x;
        __syncthreads();
    }
    if (t < SCAN_NBLK) g_part[t] = sh[t] - v;          // exclusive
    if (t == SCAN_NBLK - 1) g_rowptr[N_NODES] = sh[t]; // grand total
}

__global__ void k_writeptr() {
    __shared__ int sh[256];
    int b = blockIdx.x, t = threadIdx.x;
    int base = b * SCAN_TILE + t * 4;
    int c0 = 0, c1 = 0, c2 = 0, c3 = 0;
    if (base + 0 < N_NODES) c0 = g_cnt[base + 0];
    if (base + 1 < N_NODES) c1 = g_cnt[base + 1];
    if (base + 2 < N_NODES) c2 = g_cnt[base + 2];
    if (base + 3 < N_NODES) c3 = g_cnt[base + 3];
    int s = c0 + c1 + c2 + c3;
    sh[t] = s;
    __syncthreads();
    for (int off = 1; off < 256; off <<= 1) {
        int x = (t >= off) ? sh[t - off] : 0;
        __syncthreads();
        sh[t] += x;
        __syncthreads();
    }
    int run = g_part[b] + (sh[t] - s);
    if (base + 0 < N_NODES) { g_rowptr[base + 0] = run; g_fill[base + 0] = run; run += c0; }
    if (base + 1 < N_NODES) { g_rowptr[base + 1] = run; g_fill[base + 1] = run; run += c1; }
    if (base + 2 < N_NODES) { g_rowptr[base + 2] = run; g_fill[base + 2] = run; run += c2; }
    if (base + 3 < N_NODES) { g_rowptr[base + 3] = run; g_fill[base + 3] = run; run += c3; }
}

// ---------------- scatter edges into CSR (paired 8-byte stores) ------------
__global__ void k_scatter(const void* __restrict__ ei,
                          const float* __restrict__ ew) {
    int is64 = g_is64;
    int e = blockIdx.x * blockDim.x + threadIdx.x;
    if (e < N_EDGES) {
        int r = load_edge_idx(ei, e, is64);
        int c = load_edge_idx(ei, (long long)N_EDGES + e, is64);
        int pos = atomicAdd(&g_fill[r], 1);
        g_cw[pos] = make_int2(c, __float_as_int(ew[e]));
    }
}

// ---------------- pull-based SpMM core -------------------------------------
// One warp per destination node; lane owns 2 consecutive dims. Edge pairs
// staged in registers 32 at a time and broadcast via shfl.
__device__ __forceinline__ void spmm_row(const float* __restrict__ src,
                                         int row, int lane,
                                         float& a0, float& a1) {
    int start = g_rowptr[row];
    int end   = g_rowptr[row + 1];
    a0 = 0.f; a1 = 0.f;
    for (int base = start; base < end; base += 32) {
        int j = base + lane;
        int2 cw = make_int2(0, 0);
        if (j < end) cw = g_cw[j];
        int m = end - base; if (m > 32) m = 32;
        #pragma unroll 8
        for (int k = 0; k < m; ++k) {
            int   cc = __shfl_sync(0xffffffffu, cw.x, k);
            float wk = __int_as_float(__shfl_sync(0xffffffffu, cw.y, k));
            float2 v = __ldg((const float2*)(src + ((size_t)cc << 6) + 2 * lane));
            a0 = fmaf(wk, v.x, a0);
            a1 = fmaf(wk, v.y, a1);
        }
    }
}

// hops 1 and 2: sel==0: A->B ; sel==1: B->C
__global__ void __launch_bounds__(256) k_spmm(int sel) {
    const float* __restrict__ src = sel ? g_bufB : g_bufA;
    float*       __restrict__ dst = sel ? g_bufC : g_bufB;
    int warp = (blockIdx.x * blockDim.x + threadIdx.x) >> 5;
    int lane = threadIdx.x & 31;
    if (warp >= N_NODES) return;
    float a0, a1;
    spmm_row(src, warp, lane, a0, a1);
    *(float2*)(dst + ((size_t)warp << 6) + 2 * lane) = make_float2(a0, a1);
}

// hop 3 fused with finalization:
// out_row = (emb0 + h1 + h2 + h3) * 0.25, written directly to d_out
__global__ void __launch_bounds__(256) k_spmm_last(const float* __restrict__ users,
                                                   const float* __restrict__ items,
                                                   float* __restrict__ out) {
    int warp = (blockIdx.x * blockDim.x + threadIdx.x) >> 5;
    int lane = threadIdx.x & 31;
    if (warp >= N_NODES) return;
    float a0, a1;
    spmm_row(g_bufC, warp, lane, a0, a1);   // h3 partial for this row

    size_t ro = ((size_t)warp << 6) + 2 * lane;
    const float* e0p = (warp < NUM_USERS)
                     ? (users + ro)
                     : (items + ro - (size_t)U_ELEMS);
    float2 e0 = *(const float2*)e0p;
    float2 h1 = *(const float2*)(g_bufB + ro);
    float2 h2 = *(const float2*)(g_bufC + ro);

    float o0 = (e0.x + h1.x + h2.x + a0) * 0.25f;
    float o1 = (e0.y + h1.y + h2.y + a1) * 0.25f;

    float* op = (warp < NUM_USERS)
              ? (out + ro)                                     // u_final
              : (out + 2 * (size_t)U_ELEMS + (ro - U_ELEMS));  // i_final
    *(float2*)op = make_float2(o0, o1);
}

// ---------------- launch ----------------------------------------------------
extern "C" void kernel_launch(void* const* d_in, const int* in_sizes, int n_in,
                              void* d_out, int out_size) {
    const float* users = (const float*)d_in[0];
    const float* items = (const float*)d_in[1];
    const void*  ei    = d_in[2];   // int64 or int32, detected on device
    const float* ew    = (const float*)d_in[3];
    float* out = (float*)d_out;

    k_detect<<<1, 32>>>((const int*)ei);

    {   // emb0 -> A, echo copies -> out, zero counts
        int total = N_NODES * DIM;
        k_init<<<(total + 255) / 256, 256>>>(users, items, out);
    }

    k_count<<<(N_EDGES + 255) / 256, 256>>>(ei);

    k_partials <<<SCAN_NBLK, 256>>>();
    k_scanparts<<<1, 256>>>();
    k_writeptr <<<SCAN_NBLK, 256>>>();

    k_scatter<<<(N_EDGES + 255) / 256, 256>>>(ei, ew);

    {
        int threads = N_NODES * 32;
        int blocks = (threads + 255) / 256;
        k_spmm<<<blocks, 256>>>(0);                       // A -> B (h1)
        k_spmm<<<blocks, 256>>>(1);                       // B -> C (h2)
        k_spmm_last<<<blocks, 256>>>(users, items, out);  // C -> out (fused)
    }
}

// round 4
// speedup vs baseline: 2.0673x; 1.1271x over previous
#include <cuda_runtime.h>
#include <cuda_fp16.h>

#define NUM_USERS 100000
#define NUM_ITEMS 50000
#define N_NODES   150000
#define DIM       64
#define N_EDGES   4800000

#define U_ELEMS (NUM_USERS * DIM)   // 6,400,000
#define I_ELEMS (NUM_ITEMS * DIM)   // 3,200,000

#define SCAN_TILE 1024
#define SCAN_NBLK ((N_NODES + SCAN_TILE - 1) / SCAN_TILE)   // 147

// ---------------- static device scratch (no dynamic allocation allowed) ----
// Node features stored as fp16 pairs: row = 32 half2 = 128 bytes.
__device__ __half2 g_x0h[(size_t)N_NODES * 32];   // emb0   (fp16)
__device__ __half2 g_h1h[(size_t)N_NODES * 32];   // hop 1  (fp16)
__device__ __half2 g_h2h[(size_t)N_NODES * 32];   // hop 2  (fp16)
__device__ int   g_rowptr[N_NODES + 1];
__device__ int   g_cnt [N_NODES];
__device__ int   g_fill[N_NODES];
__device__ int   g_part[SCAN_NBLK];
__device__ int2  g_cw  [N_EDGES];                 // interleaved {col, w_bits(fp32)}
__device__ int   g_is64;

// ---------------- detect dtype (int64 vs int32) + zero counters ------------
// Node ids < 150000 (< 2^31). Little-endian int64 => every odd 32-bit word of
// the first 32 elements is 0; for int32 that's ~impossible.
__global__ void k_detect_zero(const int* __restrict__ ei32) {
    int i = blockIdx.x * blockDim.x + threadIdx.x;
    if (i < N_NODES) g_cnt[i] = 0;
    if (blockIdx.x == 0 && threadIdx.x < 32) {
        int v = ei32[2 * threadIdx.x + 1];
        unsigned b = __ballot_sync(0xffffffffu, v == 0);
        if (threadIdx.x == 0) g_is64 = (b == 0xffffffffu) ? 1 : 0;
    }
}

__device__ __forceinline__ int load_edge_idx(const void* ei, long long i, int is64) {
    if (is64) return (int)((const long long*)ei)[i];
    return ((const int*)ei)[i];
}

// ---------------- init (emb0 -> fp16, echo -> out) + row histogram ---------
// Thread e: converts concat elements [2e, 2e+1] AND counts edge e.
// out layout: [u_final | users_emb | i_final | items_emb]
__global__ void k_init_count(const float* __restrict__ users,
                             const float* __restrict__ items,
                             const void*  __restrict__ ei,
                             float* __restrict__ out) {
    int is64 = g_is64;
    int e = blockIdx.x * blockDim.x + threadIdx.x;
    if (e >= N_EDGES) return;   // N_EDGES = N_NODES*DIM/2, same grid covers both

    // --- init part: element pair j = 2e ---
    int j = 2 * e;
    float2 v;
    if (j < U_ELEMS) {
        v = *(const float2*)(users + j);
        *(float2*)(out + U_ELEMS + j) = v;                        // users echo
    } else {
        int jj = j - U_ELEMS;
        v = *(const float2*)(items + jj);
        *(float2*)(out + 2 * U_ELEMS + I_ELEMS + jj) = v;         // items echo
    }
    g_x0h[e] = __float22half2_rn(v);

    // --- count part: edge e ---
    int r = load_edge_idx(ei, e, is64);
    atomicAdd(&g_cnt[r], 1);
}

// ---------------- scan phase 1: per-1024-tile partial sums -----------------
__global__ void k_partials() {
    __shared__ int sh[256];
    int b = blockIdx.x, t = threadIdx.x;
    int base = b * SCAN_TILE + t * 4;
    int s = 0;
    #pragma unroll
    for (int k = 0; k < 4; ++k) {
        int i = base + k;
        if (i < N_NODES) s += g_cnt[i];
    }
    sh[t] = s;
    __syncthreads();
    for (int off = 128; off > 0; off >>= 1) {
        if (t < off) sh[t] += sh[t + off];
        __syncthreads();
    }
    if (t == 0) g_part[b] = sh[0];
}

// ---------------- scan phase 2: per-block, with inline scan of partials ----
__global__ void k_writeptr() {
    __shared__ int shp[256];   // scanned partials (inclusive)
    __shared__ int sh[256];
    int b = blockIdx.x, t = threadIdx.x;

    // redundant scan of the 147 tile partials in every block
    int pv = (t < SCAN_NBLK) ? g_part[t] : 0;
    shp[t] = pv;
    __syncthreads();
    for (int off = 1; off < 256; off <<= 1) {
        int x = (t >= off) ? shp[t - off] : 0;
        __syncthreads();
        shp[t] += x;
        __syncthreads();
    }
    if (b == 0 && t == SCAN_NBLK - 1) g_rowptr[N_NODES] = shp[t];
    int blockOff = (b == 0) ? 0 : shp[b - 1];

    // local exclusive scan of this tile's 1024 counts (4 per thread)
    int base = b * SCAN_TILE + t * 4;
    int c0 = 0, c1 = 0, c2 = 0, c3 = 0;
    if (base + 0 < N_NODES) c0 = g_cnt[base + 0];
    if (base + 1 < N_NODES) c1 = g_cnt[base + 1];
    if (base + 2 < N_NODES) c2 = g_cnt[base + 2];
    if (base + 3 < N_NODES) c3 = g_cnt[base + 3];
    int s = c0 + c1 + c2 + c3;
    sh[t] = s;
    __syncthreads();
    for (int off = 1; off < 256; off <<= 1) {
        int x = (t >= off) ? sh[t - off] : 0;
        __syncthreads();
        sh[t] += x;
        __syncthreads();
    }
    int run = blockOff + (sh[t] - s);
    if (base + 0 < N_NODES) { g_rowptr[base + 0] = run; g_fill[base + 0] = run; run += c0; }
    if (base + 1 < N_NODES) { g_rowptr[base + 1] = run; g_fill[base + 1] = run; run += c1; }
    if (base + 2 < N_NODES) { g_rowptr[base + 2] = run; g_fill[base + 2] = run; run += c2; }
    if (base + 3 < N_NODES) { g_rowptr[base + 3] = run; g_fill[base + 3] = run; run += c3; }
}

// ---------------- scatter edges into CSR (paired 8-byte stores) ------------
__global__ void k_scatter(const void* __restrict__ ei,
                          const float* __restrict__ ew) {
    int is64 = g_is64;
    int e = blockIdx.x * blockDim.x + threadIdx.x;
    if (e < N_EDGES) {
        int r = load_edge_idx(ei, e, is64);
        int c = load_edge_idx(ei, (long long)N_EDGES + e, is64);
        int pos = atomicAdd(&g_fill[r], 1);
        g_cw[pos] = make_int2(c, __float_as_int(ew[e]));
    }
}

// ---------------- pull-based SpMM core (fp16 gather, fp32 accumulate) ------
// One warp per destination node; lane owns 2 consecutive dims (one half2).
// Edge pairs staged in registers 32 at a time and broadcast via shfl.
__device__ __forceinline__ void spmm_row(const __half2* __restrict__ src,
                                         int row, int lane,
                                         float& a0, float& a1) {
    int start = g_rowptr[row];
    int end   = g_rowptr[row + 1];
    a0 = 0.f; a1 = 0.f;
    for (int base = start; base < end; base += 32) {
        int j = base + lane;
        int2 cw = make_int2(0, 0);
        if (j < end) cw = g_cw[j];
        int m = end - base; if (m > 32) m = 32;
        #pragma unroll 8
        for (int k = 0; k < m; ++k) {
            int   cc = __shfl_sync(0xffffffffu, cw.x, k);
            float wk = __int_as_float(__shfl_sync(0xffffffffu, cw.y, k));
            float2 v = __half22float2(__ldg(src + ((size_t)cc << 5) + lane));
            a0 = fmaf(wk, v.x, a0);
            a1 = fmaf(wk, v.y, a1);
        }
    }
}

// hops 1 and 2: sel==0: x0 -> h1 ; sel==1: h1 -> h2
__global__ void __launch_bounds__(256) k_spmm(int sel) {
    const __half2* __restrict__ src = sel ? g_h1h : g_x0h;
    __half2*       __restrict__ dst = sel ? g_h2h : g_h1h;
    int warp = (blockIdx.x * blockDim.x + threadIdx.x) >> 5;
    int lane = threadIdx.x & 31;
    if (warp >= N_NODES) return;
    float a0, a1;
    spmm_row(src, warp, lane, a0, a1);
    dst[((size_t)warp << 5) + lane] = __float22half2_rn(make_float2(a0, a1));
}

// hop 3 fused with finalization: out_row = (emb0 + h1 + h2 + h3) * 0.25
__global__ void __launch_bounds__(256) k_spmm_last(const float* __restrict__ users,
                                                   const float* __restrict__ items,
                                                   float* __restrict__ out) {
    int warp = (blockIdx.x * blockDim.x + threadIdx.x) >> 5;
    int lane = threadIdx.x & 31;
    if (warp >= N_NODES) return;
    float a0, a1;
    spmm_row(g_h2h, warp, lane, a0, a1);            // h3 partial (fp32)

    size_t ro  = ((size_t)warp << 6) + 2 * lane;    // float index
    size_t rh  = ((size_t)warp << 5) + lane;        // half2 index
    const float* e0p = (warp < NUM_USERS)
                     ? (users + ro)
                     : (items + ro - (size_t)U_ELEMS);
    float2 e0 = *(const float2*)e0p;                // exact fp32 emb0
    float2 h1 = __half22float2(g_h1h[rh]);
    float2 h2 = __half22float2(g_h2h[rh]);

    float o0 = (e0.x + h1.x + h2.x + a0) * 0.25f;
    float o1 = (e0.y + h1.y + h2.y + a1) * 0.25f;

    float* op = (warp < NUM_USERS)
              ? (out + ro)                                     // u_final
              : (out + 2 * (size_t)U_ELEMS + (ro - U_ELEMS));  // i_final
    *(float2*)op = make_float2(o0, o1);
}

// ---------------- launch ----------------------------------------------------
extern "C" void kernel_launch(void* const* d_in, const int* in_sizes, int n_in,
                              void* d_out, int out_size) {
    const float* users = (const float*)d_in[0];
    const float* items = (const float*)d_in[1];
    const void*  ei    = d_in[2];   // int64 or int32, detected on device
    const float* ew    = (const float*)d_in[3];
    float* out = (float*)d_out;

    k_detect_zero<<<(N_NODES + 255) / 256, 256>>>((const int*)ei);

    // init (emb0->fp16, echoes->out) fused with destination-row histogram
    k_init_count<<<(N_EDGES + 255) / 256, 256>>>(users, items, ei, out);

    k_partials<<<SCAN_NBLK, 256>>>();
    k_writeptr<<<SCAN_NBLK, 256>>>();

    k_scatter<<<(N_EDGES + 255) / 256, 256>>>(ei, ew);

    {
        int threads = N_NODES * 32;
        int blocks = (threads + 255) / 256;
        k_spmm<<<blocks, 256>>>(0);                       // x0 -> h1
        k_spmm<<<blocks, 256>>>(1);                       // h1 -> h2
        k_spmm_last<<<blocks, 256>>>(users, items, out);  // h2 -> out (fused)
    }
}